// round 17
// baseline (speedup 1.0000x reference)
#include <cuda_runtime.h>

#define NB 512
#define NG 100
#define NP 100
#define NE 128
#define NH 8
#define NKD 16
#define LDW 132
#define LDK 102      // kT row stride (attn)
#define LDV 68       // v local row stride (attn)

typedef unsigned long long u64;

// -------- global scratch --------
__device__ float g_q [NB * NG * NE];
__device__ float g_k [NB * NG * NE];
__device__ float g_v [NB * NG * NE];
__device__ float g_oc[NB * NG * NE];

// -------- f32x2 helpers --------
__device__ __forceinline__ void fma2(u64& d, u64 a, u64 b) {
    asm("fma.rn.f32x2 %0, %1, %2, %0;" : "+l"(d) : "l"(a), "l"(b));
}
__device__ __forceinline__ u64 add2(u64 a, u64 b) {
    u64 d; asm("add.rn.f32x2 %0, %1, %2;" : "=l"(d) : "l"(a), "l"(b)); return d;
}
__device__ __forceinline__ u64 pk(float lo, float hi) {
    u64 d; asm("mov.b64 %0, {%1, %2};" : "=l"(d) : "f"(lo), "f"(hi)); return d;
}
__device__ __forceinline__ void unpk(u64 a, float& lo, float& hi) {
    asm("mov.b64 {%0, %1}, %2;" : "=f"(lo), "=f"(hi) : "l"(a));
}
__device__ __forceinline__ float f2sum(u64 a) {
    float lo, hi; unpk(a, lo, hi); return lo + hi;
}

// -------- GEMM core: rows rbase..rbase+8 x 64-col half (conflict-free) --------
__device__ __forceinline__ void gemm_half(const float* __restrict__ sA,
                                          const float* __restrict__ swt,
                                          u64 (&acc)[9][2], int lane, int rbase) {
    const ulonglong2* w0p = (const ulonglong2*)(swt + lane * LDW);
    const ulonglong2* w1p = (const ulonglong2*)(swt + (lane + 32) * LDW);
    const float* a0 = sA + rbase * NE;
    #pragma unroll 2
    for (int e4 = 0; e4 < 32; ++e4) {
        ulonglong2 w0 = w0p[e4], w1 = w1p[e4];
        const float* ar = a0 + 4 * e4;
        #pragma unroll
        for (int i = 0; i < 9; ++i) {
            ulonglong2 a = *(const ulonglong2*)(ar + i * NE);
            fma2(acc[i][0], a.x, w0.x); fma2(acc[i][0], a.y, w0.y);
            fma2(acc[i][1], a.x, w1.x); fma2(acc[i][1], a.y, w1.y);
        }
    }
}

// stage transposed weight half: swt[n][e] = W[e][half*64+n]
__device__ __forceinline__ void stage_wt_half(const float* __restrict__ W,
                                              float* __restrict__ swt,
                                              int half, int t) {
    for (int idx = t; idx < 2048; idx += 384) {
        int n = idx & 63, e = (idx >> 6) << 2;
        int ng = half * 64 + n;
        float4 v;
        v.x = __ldg(W + (e + 0) * NE + ng);
        v.y = __ldg(W + (e + 1) * NE + ng);
        v.z = __ldg(W + (e + 2) * NE + ng);
        v.w = __ldg(W + (e + 3) * NE + ng);
        *(float4*)(swt + n * LDW + e) = v;
    }
}

// stage row-block (already WT-layout source, e.g. enc): swt[n][e] = S[(half*64+n)][e]
__device__ __forceinline__ void stage_rows_half(const float* __restrict__ S,
                                                float* __restrict__ swt,
                                                int half, int t, int nrows) {
    for (int idx = t; idx < 2048; idx += 384) {
        int n = idx >> 5, e4 = idx & 31;
        int r = half * 64 + n;
        int rc = r < nrows ? r : nrows - 1;     // clamp (garbage masked later)
        *(float4*)(swt + n * LDW + 4 * e4) = *(const float4*)(S + rc * NE + 4 * e4);
    }
}

// ==================== fused q/k/v projections: grid (NB, 3) ====================
__global__ __launch_bounds__(384, 2)
void qkv_kernel(const float* __restrict__ in2, const float* __restrict__ enc,
                const float* __restrict__ Wq, const float* __restrict__ Wk,
                const float* __restrict__ Wv, const float* __restrict__ rem,
                const float* __restrict__ in1)
{
    extern __shared__ float sm[];
    float* sA  = sm;                      // 100 x 128
    float* swt = sm + 12800;              // 64 x 132
    float* sq0 = sm + 12800 + 64 * LDW;   // 128
    const int b = blockIdx.x, by = blockIdx.y;
    const int t = threadIdx.x, lane = t & 31, warp = t >> 5;
    int rbase = warp * 9; if (rbase > 91) rbase = 91;

    const float* A = (by == 0) ? (in2 + (size_t)b * NG * NE)
                               : (enc + (size_t)b * NP * NE);
    const float* W = (by == 0) ? (Wq + NE * NE) : (by == 1) ? Wk : Wv;
    float* Cb = ((by == 0) ? g_q : (by == 1) ? g_k : g_v) + (size_t)b * NG * NE;

    const float4* Ab4 = (const float4*)A;
    for (int idx = t; idx < 3200; idx += 384)
        ((float4*)sA)[idx] = Ab4[idx];
    if (by == 0 && t < NE) {
        const float* i1 = in1 + (size_t)b * NE;
        float s = 0.f;
        #pragma unroll 8
        for (int e = 0; e < NE; ++e) s += i1[e] * __ldg(Wq + e * NE + t);
        sq0[t] = s;
    }

    #pragma unroll 1
    for (int half = 0; half < 2; ++half) {
        __syncthreads();
        stage_wt_half(W, swt, half, t);
        __syncthreads();
        u64 acc[9][2];
        #pragma unroll
        for (int i = 0; i < 9; ++i) { acc[i][0] = 0ull; acc[i][1] = 0ull; }
        gemm_half(sA, swt, acc, lane, rbase);

        int n0 = half * 64 + lane;
        float ex0 = 0.f, ex1 = 0.f, wl0 = 0.f, wl1 = 0.f;
        if (by == 0) {
            ex0 = sq0[n0]; ex1 = sq0[n0 + 32];
            wl0 = __ldg(Wq + 2 * NE * NE + n0);
            wl1 = __ldg(Wq + 2 * NE * NE + n0 + 32);
        }
        #pragma unroll
        for (int i = 0; i < 9; ++i) {
            int m = rbase + i;
            float r0 = f2sum(acc[i][0]) + ex0;
            float r1 = f2sum(acc[i][1]) + ex1;
            if (by == 0) {
                float rv = __ldg(rem + (size_t)b * NG + m);
                r0 += rv * wl0; r1 += rv * wl1;
            }
            Cb[m * NE + n0]      = r0;   // overlap rows rewritten identically
            Cb[m * NE + n0 + 32] = r1;
        }
    }
}

// ==================== attention (4 heads per CTA, kT staging) ====================
__global__ __launch_bounds__(384, 2)
void attn_kernel(const float* __restrict__ mask)
{
    extern __shared__ float sm[];
    float* s_kT = sm;              // 64 x 102
    float* s_v  = sm + 64 * LDK;   // 100 x 68
    float* s_ws = sm + 64 * LDK + 100 * LDV;   // 12 x 208
    const int b = blockIdx.x, hblk = blockIdx.y;
    const int t = threadIdx.x, lane = t & 31, warp = t >> 5;

    const float* kb = g_k + (size_t)b * NG * NE + hblk * 64;
    const float* vb = g_v + (size_t)b * NG * NE + hblk * 64;
    for (int idx = t; idx < NG * 16; idx += 384) {
        int p = idx >> 4, e4 = idx & 15;
        float4 kk = *(const float4*)(kb + p * NE + 4 * e4);
        s_kT[(4 * e4 + 0) * LDK + p] = kk.x;
        s_kT[(4 * e4 + 1) * LDK + p] = kk.y;
        s_kT[(4 * e4 + 2) * LDK + p] = kk.z;
        s_kT[(4 * e4 + 3) * LDK + p] = kk.w;
        *(float4*)(s_v + p * LDV + 4 * e4) = *(const float4*)(vb + p * NE + 4 * e4);
    }
    __syncthreads();

    const float* qb    = g_q + (size_t)b * NG * NE;
    const float* maskb = mask + (size_t)b * NG * NP;
    float* ocb = g_oc + (size_t)b * NG * NE;

    for (int task = warp; task < (NG / 4) * 4; task += 12) {
        int hl = task & 3;
        int gb = (task >> 2) * 4;
        const float* kTh = s_kT + (hl * NKD) * LDK;
        int colbase = hblk * 64 + hl * NKD;

        u64 a0[4] = {0,0,0,0}, a1[4] = {0,0,0,0};
        #pragma unroll
        for (int e0 = 0; e0 < NKD; e0 += 4) {
            float4 qf[4];
            #pragma unroll
            for (int g = 0; g < 4; ++g)
                qf[g] = *(const float4*)(qb + (gb + g) * NE + colbase + e0);
            #pragma unroll
            for (int e = 0; e < 4; ++e) {
                const float* kr = kTh + (e0 + e) * LDK;
                u64 k0 = *(const u64*)(kr + 2 * lane);
                u64 k1 = *(const u64*)(kr + 64 + 2 * lane);
                #pragma unroll
                for (int g = 0; g < 4; ++g) {
                    float qv = (e == 0) ? qf[g].x : (e == 1) ? qf[g].y
                             : (e == 2) ? qf[g].z : qf[g].w;
                    u64 q2 = pk(qv, qv);
                    fma2(a0[g], q2, k0);
                    fma2(a1[g], q2, k1);
                }
            }
        }

        float w[4][4];
        #pragma unroll
        for (int g = 0; g < 4; ++g) {
            int gi = gb + g;
            float x0, x1, x2, x3;
            unpk(a0[g], x0, x1);
            unpk(a1[g], x2, x3);
            float2 mA = *(const float2*)(maskb + gi * NP + 2 * lane);
            x0 = x0 * 0.25f + mA.x;
            x1 = x1 * 0.25f + mA.y;
            if (lane < 18) {
                float2 mB = *(const float2*)(maskb + gi * NP + 64 + 2 * lane);
                x2 = x2 * 0.25f + mB.x;
                x3 = x3 * 0.25f + mB.y;
            } else { x2 = -3e38f; x3 = -3e38f; }
            float mx = fmaxf(fmaxf(x0, x1), fmaxf(x2, x3));
            #pragma unroll
            for (int o = 16; o; o >>= 1)
                mx = fmaxf(mx, __shfl_xor_sync(0xffffffffu, mx, o));
            x0 = __expf(x0 - mx);
            x1 = __expf(x1 - mx);
            x2 = (lane < 18) ? __expf(x2 - mx) : 0.f;
            x3 = (lane < 18) ? __expf(x3 - mx) : 0.f;
            float sum = x0 + x1 + x2 + x3;
            #pragma unroll
            for (int o = 16; o; o >>= 1)
                sum += __shfl_xor_sync(0xffffffffu, sum, o);
            float inv = 1.f / sum;
            w[g][0] = x0 * inv; w[g][1] = x1 * inv;
            w[g][2] = x2 * inv; w[g][3] = x3 * inv;
        }

        float* wsl = s_ws + warp * 208;
        int c4 = lane >> 3, pgl = lane & 7;
        #pragma unroll
        for (int sb = 0; sb < 2; ++sb) {
            int ga = 2 * sb, gbd = 2 * sb + 1;
            float* w0 = wsl;
            float* w1 = wsl + 104;
            *(float2*)(w0 + 2 * lane) = make_float2(w[ga][0], w[ga][1]);
            *(float2*)(w1 + 2 * lane) = make_float2(w[gbd][0], w[gbd][1]);
            if (lane < 18) {
                *(float2*)(w0 + 64 + 2 * lane) = make_float2(w[ga][2], w[ga][3]);
                *(float2*)(w1 + 64 + 2 * lane) = make_float2(w[gbd][2], w[gbd][3]);
            }
            __syncwarp();
            u64 o00 = 0, o01 = 0, o10 = 0, o11 = 0;
            #pragma unroll
            for (int pp = 0; pp < 13; ++pp) {
                int p = pgl + 8 * pp;
                if (p < NP) {
                    ulonglong2 vv = *((const ulonglong2*)(s_v + p * LDV + hl * NKD) + c4);
                    u64 aa = pk(w0[p], w0[p]);
                    u64 cc = pk(w1[p], w1[p]);
                    fma2(o00, aa, vv.x); fma2(o01, aa, vv.y);
                    fma2(o10, cc, vv.x); fma2(o11, cc, vv.y);
                }
            }
            #pragma unroll
            for (int o = 4; o; o >>= 1) {
                o00 = add2(o00, __shfl_xor_sync(0xffffffffu, o00, o));
                o01 = add2(o01, __shfl_xor_sync(0xffffffffu, o01, o));
                o10 = add2(o10, __shfl_xor_sync(0xffffffffu, o10, o));
                o11 = add2(o11, __shfl_xor_sync(0xffffffffu, o11, o));
            }
            if (pgl == 0) {
                ulonglong2 r0; r0.x = o00; r0.y = o01;
                ulonglong2 r1; r1.x = o10; r1.y = o11;
                *(ulonglong2*)(ocb + (gb + ga)  * NE + colbase + 4 * c4) = r0;
                *(ulonglong2*)(ocb + (gb + gbd) * NE + colbase + 4 * c4) = r1;
            }
            __syncwarp();
        }
    }
}

// ==================== fused mh-projection + pointer softmax ====================
// Phase A: mh = oc @ Wc + bc (results in registers)
// Phase B: mh overwrites oc tile in smem
// Phase C: score = mh @ enc^T ; probs = softmax(10*tanh(score/sqrt(128)) + mask)
__global__ __launch_bounds__(384, 2)
void pointer_kernel(const float* __restrict__ mask, const float* __restrict__ enc,
                    const float* __restrict__ Wc, const float* __restrict__ bc,
                    float* __restrict__ out)
{
    extern __shared__ float sm[];
    float* sA  = sm;            // oc -> mh, 100 x 128
    float* swt = sm + 12800;    // WcT half / enc half, 64 x 132
    const int b = blockIdx.x, t = threadIdx.x, lane = t & 31, warp = t >> 5;
    int rbase = warp * 9; if (rbase > 91) rbase = 91;

    const float4* Ab4 = (const float4*)(g_oc + (size_t)b * NG * NE);
    for (int idx = t; idx < 3200; idx += 384)
        ((float4*)sA)[idx] = Ab4[idx];

    // ---- Phase A: mh rows in registers ----
    float mhv[9][4];
    #pragma unroll 1
    for (int half = 0; half < 2; ++half) {
        __syncthreads();
        stage_wt_half(Wc, swt, half, t);
        __syncthreads();
        u64 acc[9][2];
        #pragma unroll
        for (int i = 0; i < 9; ++i) { acc[i][0] = 0ull; acc[i][1] = 0ull; }
        gemm_half(sA, swt, acc, lane, rbase);
        int n0 = half * 64 + lane;
        float ex0 = __ldg(bc + n0), ex1 = __ldg(bc + n0 + 32);
        #pragma unroll
        for (int i = 0; i < 9; ++i) {
            mhv[i][2 * half + 0] = f2sum(acc[i][0]) + ex0;
            mhv[i][2 * half + 1] = f2sum(acc[i][1]) + ex1;
        }
    }

    // ---- Phase B: write mh over the oc tile ----
    __syncthreads();          // all oc reads done
    #pragma unroll
    for (int i = 0; i < 9; ++i) {
        int m = rbase + i;    // overlap rows written identically by warps 10/11
        sA[m * NE + lane]      = mhv[i][0];
        sA[m * NE + lane + 32] = mhv[i][1];
        sA[m * NE + lane + 64] = mhv[i][2];
        sA[m * NE + lane + 96] = mhv[i][3];
    }

    // ---- Phase C: score GEMM + clipped softmax ----
    const float* encb = enc + (size_t)b * NP * NE;
    float sc[9][4];
    #pragma unroll 1
    for (int half = 0; half < 2; ++half) {
        __syncthreads();
        stage_rows_half(encb, swt, half, t, NP);
        __syncthreads();
        u64 acc[9][2];
        #pragma unroll
        for (int i = 0; i < 9; ++i) { acc[i][0] = 0ull; acc[i][1] = 0ull; }
        gemm_half(sA, swt, acc, lane, rbase);
        #pragma unroll
        for (int i = 0; i < 9; ++i) {
            sc[i][2 * half + 0] = f2sum(acc[i][0]);
            sc[i][2 * half + 1] = f2sum(acc[i][1]);
        }
    }

    const float* maskb = mask + (size_t)b * NG * NP;
    const float invsq = 0.08838834764831845f;   // 1/sqrt(128)
    float* outb = out + (size_t)b * NG * NP;

    #pragma unroll
    for (int i = 0; i < 9; ++i) {
        int g = rbase + i;
        float x[4]; float mx = -3e38f;
        #pragma unroll
        for (int r = 0; r < 4; ++r) {
            int p = lane + 32 * r;
            float s = -3e38f;
            if (p < NP)
                s = 10.f * tanhf(sc[i][r] * invsq) + __ldg(maskb + g * NP + p);
            x[r] = s; mx = fmaxf(mx, s);
        }
        #pragma unroll
        for (int o = 16; o; o >>= 1)
            mx = fmaxf(mx, __shfl_xor_sync(0xffffffffu, mx, o));
        float sum = 0.f;
        #pragma unroll
        for (int r = 0; r < 4; ++r) {
            float e_ = (x[r] > -1e37f) ? __expf(x[r] - mx) : 0.f;
            x[r] = e_; sum += e_;
        }
        #pragma unroll
        for (int o = 16; o; o >>= 1)
            sum += __shfl_xor_sync(0xffffffffu, sum, o);
        float inv = 1.f / sum;
        #pragma unroll
        for (int r = 0; r < 4; ++r) {
            int p = lane + 32 * r;
            if (p < NP) outb[g * NP + p] = x[r] * inv;   // overlap rows rewritten identically
        }
    }
}

// ==================== launcher ====================
extern "C" void kernel_launch(void* const* d_in, const int* in_sizes, int n_in,
                              void* d_out, int out_size)
{
    const float* in1  = (const float*)d_in[0];
    const float* in2  = (const float*)d_in[1];
    const float* rem  = (const float*)d_in[2];
    const float* mask = (const float*)d_in[3];
    const float* enc  = (const float*)d_in[4];
    const float* Wq   = (const float*)d_in[5];
    const float* Wk   = (const float*)d_in[6];
    const float* Wv   = (const float*)d_in[7];
    const float* Wc   = (const float*)d_in[8];
    const float* bc   = (const float*)d_in[9];
    float* out = (float*)d_out;

    const int smProj = (12800 + 64 * LDW + 128) * 4;           // 85504
    const int smAttn = (64 * LDK + 100 * LDV + 12 * 208) * 4;  // 63296
    cudaFuncSetAttribute(qkv_kernel,
                         cudaFuncAttributeMaxDynamicSharedMemorySize, smProj);
    cudaFuncSetAttribute(attn_kernel,
                         cudaFuncAttributeMaxDynamicSharedMemorySize, smAttn);
    cudaFuncSetAttribute(pointer_kernel,
                         cudaFuncAttributeMaxDynamicSharedMemorySize, smProj);

    qkv_kernel<<<dim3(NB, 3), 384, smProj>>>(in2, enc, Wq, Wk, Wv, rem, in1);
    attn_kernel<<<dim3(NB, 2), 384, smAttn>>>(mask);
    pointer_kernel<<<NB, 384, smProj>>>(mask, enc, Wc, bc, out);
}